// round 16
// baseline (speedup 1.0000x reference)
#include <cuda_runtime.h>
#include <math.h>

// ---------------- problem constants ----------------
#define NB      64
#define DMODEL  2048
#define DINNER  4096
#define DSTATE  16
#define DTRANK  128
#define FE      512

// ---------------- scratch layout (floats) ----------------
#define OFF_F     0          // 64*512      conv relu-sum accumulator
#define OFF_U     163840     // 128*2048    mamba input u (rows = b*2+l)
#define OFF_XZ    425984     // 128*8192    xz = u @ W_in^T (split-K atomic)
#define OFF_XS    1474560    // 128*4096    silu(conv1d(x))
#define OFF_XDBL  1998848    // 128*160     x_dbl
#define OFF_DT    2019328    // 128*4096    dt (softplus)
#define OFF_Y     2543616    // 64*4096     gated scan output at l=1
#define OFF_FEAT  2805760    // 64*2048     y @ W_out^T
#define OFF_WT    2936832    // 76*512 uint2: packed tf32 conv weights (k,k+4 pairs)
#define SCRATCH_TOTAL 3014656

__device__ float g_scratch[SCRATCH_TOTAL];

// conv_tc dynamic smem layout (bytes) — 64-channel weight chunks (R8 proven config)
#define CONV_SMEM_W     0                    // 76*68 uint2 = 41344
#define CONV_SMEM_ACC   41344                // 2*512 float = 4096
#define CONV_SMEM_IN    45440                // 2*3*35*35 tf32 = 29400
#define CONV_SMEM_TOTAL 74840

// ---------------- tf32 mma helpers ----------------
__device__ __forceinline__ unsigned f2tf32(float v) {
    unsigned r;
    asm("cvt.rna.tf32.f32 %0, %1;" : "=r"(r) : "f"(v));
    return r;
}
__device__ __forceinline__ void mma_tf32(float c[4],
                                         unsigned a0, unsigned a1, unsigned a2, unsigned a3,
                                         unsigned b0, unsigned b1) {
    asm volatile(
        "mma.sync.aligned.m16n8k8.row.col.f32.tf32.tf32.f32 "
        "{%0,%1,%2,%3}, {%4,%5,%6,%7}, {%8,%9}, {%0,%1,%2,%3};"
        : "+f"(c[0]), "+f"(c[1]), "+f"(c[2]), "+f"(c[3])
        : "r"(a0), "r"(a1), "r"(a2), "r"(a3), "r"(b0), "r"(b1));
}
// packed (hi,lo) tf32 split of a float
__device__ __forceinline__ uint2 split_tf32(float v) {
    unsigned h = f2tf32(v);
    return make_uint2(h, f2tf32(v - __uint_as_float(h)));
}

// ---------------- fused prep: conv weight pack + zero ALL accumulators ----------------
#define PZ_WT   38912
#define PZ_XD   59392
#define PZ_FT   190464
#define PZ_F    223232
#define PZ_TOT  1271808
__global__ void prep_zero_kernel(const float* __restrict__ w, float* S) {
    int i = blockIdx.x * blockDim.x + threadIdx.x;
    if (i >= PZ_TOT) return;
    if (i < PZ_WT) {
        int kp = i >> 9, co = i & 511;
        int k0 = (kp >> 2) * 8 + (kp & 3);
        int k1 = k0 + 4;
        float v0 = (k0 < 147) ? w[co * 147 + k0] : 0.f;
        float v1 = (k1 < 147) ? w[co * 147 + k1] : 0.f;
        ((uint2*)(S + OFF_WT))[kp * 512 + co] = make_uint2(f2tf32(v0), f2tf32(v1));
    } else if (i < PZ_XD) {
        S[OFF_XDBL + (i - PZ_WT)] = 0.f;
    } else if (i < PZ_FT) {
        S[OFF_FEAT + (i - PZ_XD)] = 0.f;
    } else if (i < PZ_F) {
        S[OFF_F + (i - PZ_FT)] = 0.f;
    } else {
        S[OFF_XZ + (i - PZ_F)] = 0.f;
    }
}

// ---------------- conv 7x7 s4 p3 + bias + relu + spatial-sum (tensor cores) ----------
// (R8 proven config — unchanged)
__global__ void __launch_bounds__(128)
conv_tc_kernel(const float* __restrict__ x, const uint2* __restrict__ wTp,
               const float* __restrict__ bias, float* __restrict__ f_accum)
{
    extern __shared__ __align__(16) char smem[];
    uint2*    s_w  = reinterpret_cast<uint2*>(smem + CONV_SMEM_W);       // [76][68]
    float*    s_acc = reinterpret_cast<float*>(smem + CONV_SMEM_ACC);    // [2][512]
    unsigned* s_in  = reinterpret_cast<unsigned*>(smem + CONV_SMEM_IN);  // [2][3][35][35] tf32

    const int t    = threadIdx.x;
    const int tile = blockIdx.x;
    const int bp   = blockIdx.y;
    const int oh_base = (tile / 7) * 8;
    const int ow_base = (tile % 7) * 8;
    const int ih0 = oh_base * 4 - 3;
    const int iw0 = ow_base * 4 - 3;

    for (int i = t; i < 1024; i += 128) s_acc[i] = 0.f;

    for (int i = t; i < 2 * 3 * 1225; i += 128) {
        int img = i / 3675;
        int rem = i - img * 3675;
        int ci  = rem / 1225; rem -= ci * 1225;
        int r = rem / 35, c = rem - (rem / 35) * 35;
        int ih = ih0 + r, iw = iw0 + c;
        float v = 0.f;
        int b = bp * 2 + img;
        if ((unsigned)ih < 224u && (unsigned)iw < 224u)
            v = x[((b * 3 + ci) * 224 + ih) * 224 + iw];
        s_in[(img * 3 + ci) * 1225 + r * 35 + c] = f2tf32(v);
    }

    const int lane = t & 31;
    const int w    = t >> 5;
    const int img  = w >> 1;
    const int half = w & 1;
    const int q    = lane >> 2;
    const int j    = lane & 3;
    const int ya = half * 16;
    const int xb = q * 4;
    const unsigned* my_in = s_in + img * 3675 + ya * 35 + xb;

    int o0[19], o1[19];
    #pragma unroll
    for (int ks = 0; ks < 19; ++ks) {
        int k0 = ks * 8 + j, k1 = k0 + 4;
        int kk0 = min(k0, 146), kk1 = min(k1, 146);
        int ci0 = kk0 / 49, r0 = kk0 - ci0 * 49;
        int kh0 = r0 / 7,  kw0 = r0 - kh0 * 7;
        int ci1 = kk1 / 49, r1 = kk1 - ci1 * 49;
        int kh1 = r1 / 7,  kw1 = r1 - kh1 * 7;
        o0[ks] = ci0 * 1225 + kh0 * 35 + kw0;
        o1[ks] = ci1 * 1225 + kh1 * 35 + kw1;
    }

    for (int n0 = 0; n0 < 512; n0 += 64) {
        __syncthreads();
        {
            const uint4* src = reinterpret_cast<const uint4*>(wTp);
            uint4* dst = reinterpret_cast<uint4*>(s_w);
            for (int i = t; i < 76 * 32; i += 128) {
                int row = i >> 5, c = i & 31;
                dst[row * 34 + c] = src[row * 256 + (n0 >> 1) + c];
            }
        }
        __syncthreads();

        float c[2][8][4];
        #pragma unroll
        for (int f2 = 0; f2 < 2; ++f2)
            #pragma unroll
            for (int nf = 0; nf < 8; ++nf)
                #pragma unroll
                for (int u2 = 0; u2 < 4; ++u2) c[f2][nf][u2] = 0.f;

        #pragma unroll
        for (int ks = 0; ks < 19; ++ks) {
            int p0 = o0[ks], p1 = o1[ks];
            unsigned aA0 = my_in[p0];
            unsigned aA1 = my_in[p0 + 140];
            unsigned aA2 = my_in[p1];
            unsigned aA3 = my_in[p1 + 140];
            unsigned aB0 = my_in[p0 + 280];
            unsigned aB1 = my_in[p0 + 420];
            unsigned aB2 = my_in[p1 + 280];
            unsigned aB3 = my_in[p1 + 420];
            const uint2* wr = s_w + (ks * 4 + j) * 68 + q;
            #pragma unroll
            for (int nf = 0; nf < 8; ++nf) {
                uint2 b2 = wr[nf * 8];
                mma_tf32(c[0][nf], aA0, aA1, aA2, aA3, b2.x, b2.y);
                mma_tf32(c[1][nf], aB0, aB1, aB2, aB3, b2.x, b2.y);
            }
        }

        #pragma unroll
        for (int nf = 0; nf < 8; ++nf) {
            int ca = n0 + nf * 8 + 2 * j;
            float bva = bias[ca], bvb = bias[ca + 1];
            float va = fmaxf(c[0][nf][0] + bva, 0.f) + fmaxf(c[0][nf][2] + bva, 0.f)
                     + fmaxf(c[1][nf][0] + bva, 0.f) + fmaxf(c[1][nf][2] + bva, 0.f);
            float vb = fmaxf(c[0][nf][1] + bvb, 0.f) + fmaxf(c[0][nf][3] + bvb, 0.f)
                     + fmaxf(c[1][nf][1] + bvb, 0.f) + fmaxf(c[1][nf][3] + bvb, 0.f);
            #pragma unroll
            for (int off = 16; off >= 4; off >>= 1) {
                va += __shfl_down_sync(0xffffffffu, va, off);
                vb += __shfl_down_sync(0xffffffffu, vb, off);
            }
            if (lane < 4) {
                atomicAdd(&s_acc[img * 512 + ca], va);
                atomicAdd(&s_acc[img * 512 + ca + 1], vb);
            }
        }
    }

    __syncthreads();
    for (int i = t; i < 1024; i += 128) {
        int im = i >> 9, ch = i & 511;
        atomicAdd(&f_accum[(bp * 2 + im) * 512 + ch], s_acc[im * 512 + ch]);
    }
}

// ---------------- BM=128 3xTF32 GEMM, packed (hi,lo) uint2 fragments ----------------
// strides in uint2 units: SA=132, SW=68 (2*S % 32 == 8 -> conflict-free phases)
#define GT_SA 132
#define GT_SW 68
__global__ void __launch_bounds__(256)
gemm_tc_kernel(const float* __restrict__ A, int lda,
               const float* __restrict__ W,
               const float* __restrict__ bias, int act,
               float* __restrict__ C, int ldc,
               int M, int N, int K, int atomic)
{
    __shared__ uint2 sA[16 * GT_SA];   // [k][m] (hi,lo)
    __shared__ uint2 sW[16 * GT_SW];   // [k][n] (hi,lo)

    const int bm = blockIdx.y * 128;
    const int bn = blockIdx.x * 64;
    const int t = threadIdx.x, lane = t & 31, w = t >> 5;
    const int kPer = K / gridDim.z;
    const int kBeg = blockIdx.z * kPer;
    const int kEnd = kBeg + kPer;

    const int rA0 = t >> 2,   cA = t & 3;
    const int rA1 = rA0 + 64;
    const int gA0 = min(bm + rA0, M - 1);
    const int gA1 = min(bm + rA1, M - 1);
    const int gW  = bn + rA0;
    const bool wOk = (gW < N);

    float acc[8][4];
    #pragma unroll
    for (int nf = 0; nf < 8; ++nf)
        #pragma unroll
        for (int u2 = 0; u2 < 4; ++u2) acc[nf][u2] = 0.f;

    float4 rAv0 = *reinterpret_cast<const float4*>(A + (size_t)gA0 * lda + kBeg + cA * 4);
    float4 rAv1 = *reinterpret_cast<const float4*>(A + (size_t)gA1 * lda + kBeg + cA * 4);
    float4 rWv  = wOk ? *reinterpret_cast<const float4*>(W + (size_t)gW * K + kBeg + cA * 4)
                      : make_float4(0.f, 0.f, 0.f, 0.f);

    for (int k0 = kBeg; k0 < kEnd; k0 += 16) {
        {
            float vv0[4] = {rAv0.x, rAv0.y, rAv0.z, rAv0.w};
            float vv1[4] = {rAv1.x, rAv1.y, rAv1.z, rAv1.w};
            float vvW[4] = {rWv.x, rWv.y, rWv.z, rWv.w};
            #pragma unroll
            for (int e = 0; e < 4; ++e) {
                sA[(cA * 4 + e) * GT_SA + rA0] = split_tf32(vv0[e]);
                sA[(cA * 4 + e) * GT_SA + rA1] = split_tf32(vv1[e]);
                sW[(cA * 4 + e) * GT_SW + rA0] = split_tf32(vvW[e]);
            }
        }
        __syncthreads();

        int kn = k0 + 16;
        if (kn < kEnd) {
            rAv0 = *reinterpret_cast<const float4*>(A + (size_t)gA0 * lda + kn + cA * 4);
            rAv1 = *reinterpret_cast<const float4*>(A + (size_t)gA1 * lda + kn + cA * 4);
            if (wOk)
                rWv = *reinterpret_cast<const float4*>(W + (size_t)gW * K + kn + cA * 4);
        }

        #pragma unroll
        for (int ks = 0; ks < 2; ++ks) {
            int kb = ks * 8;
            int ar = w * 16 + (lane >> 2);
            int ac = kb + (lane & 3);
            uint2 a0 = sA[ac * GT_SA + ar];
            uint2 a1 = sA[ac * GT_SA + ar + 8];
            uint2 a2 = sA[(ac + 4) * GT_SA + ar];
            uint2 a3 = sA[(ac + 4) * GT_SA + ar + 8];

            #pragma unroll
            for (int nf = 0; nf < 8; ++nf) {
                int bc = nf * 8 + (lane >> 2);
                int br = kb + (lane & 3);
                uint2 b0 = sW[br * GT_SW + bc];
                uint2 b1 = sW[(br + 4) * GT_SW + bc];
                mma_tf32(acc[nf], a0.x, a1.x, a2.x, a3.x, b0.x, b1.x);
                mma_tf32(acc[nf], a0.x, a1.x, a2.x, a3.x, b0.y, b1.y);
                mma_tf32(acc[nf], a0.y, a1.y, a2.y, a3.y, b0.x, b1.x);
            }
        }
        __syncthreads();
    }

    const int mr0 = bm + w * 16 + (lane >> 2);
    const int nc0 = bn + (lane & 3) * 2;
    #pragma unroll
    for (int nf = 0; nf < 8; ++nf) {
        int n = nc0 + nf * 8;
        if (n >= N) continue;
        if (atomic) {
            if (mr0 < M) {
                atomicAdd(&C[(size_t)mr0 * ldc + n],     acc[nf][0]);
                atomicAdd(&C[(size_t)mr0 * ldc + n + 1], acc[nf][1]);
            }
            if (mr0 + 8 < M) {
                atomicAdd(&C[(size_t)(mr0 + 8) * ldc + n],     acc[nf][2]);
                atomicAdd(&C[(size_t)(mr0 + 8) * ldc + n + 1], acc[nf][3]);
            }
        } else {
            float b0 = bias ? bias[n] : 0.f;
            float b1 = bias ? bias[n + 1] : 0.f;
            float v00 = acc[nf][0] + b0, v01 = acc[nf][1] + b1;
            float v10 = acc[nf][2] + b0, v11 = acc[nf][3] + b1;
            if (act == 2) {
                v00 = (v00 > 20.f) ? v00 : log1pf(expf(v00));
                v01 = (v01 > 20.f) ? v01 : log1pf(expf(v01));
                v10 = (v10 > 20.f) ? v10 : log1pf(expf(v10));
                v11 = (v11 > 20.f) ? v11 : log1pf(expf(v11));
            }
            if (mr0 < M) {
                C[(size_t)mr0 * ldc + n]     = v00;
                C[(size_t)mr0 * ldc + n + 1] = v01;
            }
            if (mr0 + 8 < M) {
                C[(size_t)(mr0 + 8) * ldc + n]     = v10;
                C[(size_t)(mr0 + 8) * ldc + n + 1] = v11;
            }
        }
    }
}

// ---------------- BM=64 3xTF32 GEMM, packed (hi,lo) uint2 fragments ----------------
#define GT64_S 68
__global__ void __launch_bounds__(256)
gemm_tc64_kernel(const float* __restrict__ A, int lda,
                 const float* __restrict__ W,
                 const float* __restrict__ bias, int act,
                 float* __restrict__ C, int ldc,
                 int M, int N, int K, int atomic)
{
    __shared__ uint2 sA[16 * GT64_S];
    __shared__ uint2 sW[16 * GT64_S];

    const int bm = blockIdx.y * 64;
    const int bn = blockIdx.x * 64;
    const int t = threadIdx.x, lane = t & 31, w = t >> 5;
    const int kPer = K / gridDim.z;
    const int kBeg = blockIdx.z * kPer;
    const int kEnd = kBeg + kPer;

    const int rA = t >> 2, cA = t & 3;
    const int gA = min(bm + rA, M - 1);
    const int gW = bn + rA;
    const bool wOk = (gW < N);

    float acc[4][4];
    #pragma unroll
    for (int nf = 0; nf < 4; ++nf)
        #pragma unroll
        for (int u2 = 0; u2 < 4; ++u2) acc[nf][u2] = 0.f;

    float4 rAv = *reinterpret_cast<const float4*>(A + (size_t)gA * lda + kBeg + cA * 4);
    float4 rWv = wOk ? *reinterpret_cast<const float4*>(W + (size_t)gW * K + kBeg + cA * 4)
                     : make_float4(0.f, 0.f, 0.f, 0.f);

    for (int k0 = kBeg; k0 < kEnd; k0 += 16) {
        {
            float vvA[4] = {rAv.x, rAv.y, rAv.z, rAv.w};
            float vvW[4] = {rWv.x, rWv.y, rWv.z, rWv.w};
            #pragma unroll
            for (int e = 0; e < 4; ++e) {
                sA[(cA * 4 + e) * GT64_S + rA] = split_tf32(vvA[e]);
                sW[(cA * 4 + e) * GT64_S + rA] = split_tf32(vvW[e]);
            }
        }
        __syncthreads();

        int kn = k0 + 16;
        if (kn < kEnd) {
            rAv = *reinterpret_cast<const float4*>(A + (size_t)gA * lda + kn + cA * 4);
            if (wOk)
                rWv = *reinterpret_cast<const float4*>(W + (size_t)gW * K + kn + cA * 4);
        }

        #pragma unroll
        for (int ks = 0; ks < 2; ++ks) {
            int kb = ks * 8;
            int ar = (w & 3) * 16 + (lane >> 2);
            int ac = kb + (lane & 3);
            uint2 a0 = sA[ac * GT64_S + ar];
            uint2 a1 = sA[ac * GT64_S + ar + 8];
            uint2 a2 = sA[(ac + 4) * GT64_S + ar];
            uint2 a3 = sA[(ac + 4) * GT64_S + ar + 8];

            #pragma unroll
            for (int nf = 0; nf < 4; ++nf) {
                int bc = (w >> 2) * 32 + nf * 8 + (lane >> 2);
                int br = kb + (lane & 3);
                uint2 b0 = sW[br * GT64_S + bc];
                uint2 b1 = sW[(br + 4) * GT64_S + bc];
                mma_tf32(acc[nf], a0.x, a1.x, a2.x, a3.x, b0.x, b1.x);
                mma_tf32(acc[nf], a0.x, a1.x, a2.x, a3.x, b0.y, b1.y);
                mma_tf32(acc[nf], a0.y, a1.y, a2.y, a3.y, b0.x, b1.x);
            }
        }
        __syncthreads();
    }

    const int mr0 = bm + (w & 3) * 16 + (lane >> 2);
    const int nc0 = bn + (w >> 2) * 32 + (lane & 3) * 2;
    #pragma unroll
    for (int nf = 0; nf < 4; ++nf) {
        int n = nc0 + nf * 8;
        if (n >= N) continue;
        if (atomic) {
            if (mr0 < M) {
                atomicAdd(&C[(size_t)mr0 * ldc + n],     acc[nf][0]);
                atomicAdd(&C[(size_t)mr0 * ldc + n + 1], acc[nf][1]);
            }
            if (mr0 + 8 < M) {
                atomicAdd(&C[(size_t)(mr0 + 8) * ldc + n],     acc[nf][2]);
                atomicAdd(&C[(size_t)(mr0 + 8) * ldc + n + 1], acc[nf][3]);
            }
        } else if (act == 3) {
            float b0 = bias[n], b1 = bias[n + 1];
            #pragma unroll
            for (int h = 0; h < 2; ++h) {
                int m = mr0 + h * 8;
                if (m >= M) continue;
                float v0 = fmaxf(acc[nf][h * 2 + 0] * (1.f / 3136.f) + b0, 0.f);
                float v1 = fmaxf(acc[nf][h * 2 + 1] * (1.f / 3136.f) + b1, 0.f);
                C[(size_t)(2 * m + 1) * DMODEL + n]     = v0;
                C[(size_t)(2 * m + 1) * DMODEL + n + 1] = v1;
                C[(size_t)(2 * m) * DMODEL + (DMODEL - 1 - n)]       = v0;
                C[(size_t)(2 * m) * DMODEL + (DMODEL - 1 - (n + 1))] = v1;
            }
        } else {
            float b0 = bias ? bias[n] : 0.f;
            float b1 = bias ? bias[n + 1] : 0.f;
            if (mr0 < M) {
                C[(size_t)mr0 * ldc + n]     = acc[nf][0] + b0;
                C[(size_t)mr0 * ldc + n + 1] = acc[nf][1] + b1;
            }
            if (mr0 + 8 < M) {
                C[(size_t)(mr0 + 8) * ldc + n]     = acc[nf][2] + b0;
                C[(size_t)(mr0 + 8) * ldc + n + 1] = acc[nf][3] + b1;
            }
        }
    }
}

// ---------------- depthwise conv1d (L=2, causal k=4) + silu ----------------
__global__ void conv1d_silu_kernel(const float* __restrict__ xz, const float* __restrict__ w,
                                   const float* __restrict__ bias, float* __restrict__ xs)
{
    int idx = blockIdx.x * blockDim.x + threadIdx.x;
    if (idx >= NB * DINNER) return;
    int b = idx >> 12, e = idx & 4095;
    float x0 = xz[(2 * b) * (2 * DINNER) + e];
    float x1 = xz[(2 * b + 1) * (2 * DINNER) + e];
    float w2 = w[e * 4 + 2], w3 = w[e * 4 + 3];
    float bv = bias[e];
    float v0 = x0 * w3 + bv;
    float v1 = x0 * w2 + x1 * w3 + bv;
    xs[(2 * b) * DINNER + e]     = v0 / (1.f + expf(-v0));
    xs[(2 * b + 1) * DINNER + e] = v1 / (1.f + expf(-v1));
}

// ---------------- selective scan (L=2, closed form) + D skip + silu(z) gating --------
__global__ void scan_kernel(const float* __restrict__ xz, const float* __restrict__ xs,
                            const float* __restrict__ xdbl, const float* __restrict__ dt,
                            const float* __restrict__ A_log, const float* __restrict__ Dv,
                            float* __restrict__ y)
{
    int idx = blockIdx.x * blockDim.x + threadIdx.x;
    if (idx >= NB * DINNER) return;
    int b = idx >> 12, e = idx & 4095;

    float dt0 = dt[(2 * b) * DINNER + e];
    float dt1 = dt[(2 * b + 1) * DINNER + e];
    float x0  = xs[(2 * b) * DINNER + e];
    float x1  = xs[(2 * b + 1) * DINNER + e];
    float z1  = xz[(2 * b + 1) * (2 * DINNER) + DINNER + e];

    const float* bc0 = xdbl + (2 * b) * 160;
    const float* bc1 = xdbl + (2 * b + 1) * 160;

    float acc = 0.f;
    #pragma unroll
    for (int n = 0; n < DSTATE; ++n) {
        float Ae = -expf(A_log[e * DSTATE + n]);
        float h = dt0 * bc0[DTRANK + n] * x0;
        h = h * expf(dt1 * Ae) + dt1 * bc1[DTRANK + n] * x1;
        acc += h * bc1[DTRANK + DSTATE + n];
    }
    float yv = acc + x1 * Dv[e];
    float sg = z1 / (1.f + expf(-z1));
    y[b * DINNER + e] = yv * sg;
}

// ---------------- output heads ----------------
__global__ void heads_kernel(const float* __restrict__ feat,
                             const float* __restrict__ wxyz, const float* __restrict__ bxyz,
                             const float* __restrict__ wpqr, const float* __restrict__ bpqr,
                             float* __restrict__ out)
{
    int b = blockIdx.x / 7, j = blockIdx.x % 7;
    const float* wrow = (j < 3) ? (wxyz + j * DMODEL) : (wpqr + (j - 3) * DMODEL);
    float bias = (j < 3) ? bxyz[j] : bpqr[j - 3];

    float s = 0.f;
    for (int i = threadIdx.x; i < DMODEL; i += 128)
        s += feat[b * DMODEL + i] * wrow[i];

    __shared__ float red[4];
    #pragma unroll
    for (int off = 16; off; off >>= 1) s += __shfl_down_sync(0xffffffffu, s, off);
    if ((threadIdx.x & 31) == 0) red[threadIdx.x >> 5] = s;
    __syncthreads();
    if (threadIdx.x == 0)
        out[b * 7 + j] = red[0] + red[1] + red[2] + red[3] + bias;
}

// ---------------- launcher ----------------
extern "C" void kernel_launch(void* const* d_in, const int* in_sizes, int n_in,
                              void* d_out, int out_size)
{
    const float* x       = (const float*)d_in[0];
    const float* conv_w  = (const float*)d_in[1];
    const float* conv_b  = (const float*)d_in[2];
    const float* fc_w    = (const float*)d_in[3];
    const float* fc_b    = (const float*)d_in[4];
    const float* W_in    = (const float*)d_in[5];
    const float* c1w     = (const float*)d_in[6];
    const float* c1b     = (const float*)d_in[7];
    const float* W_xproj = (const float*)d_in[8];
    const float* W_dt    = (const float*)d_in[9];
    const float* b_dt    = (const float*)d_in[10];
    const float* A_log   = (const float*)d_in[11];
    const float* Dv      = (const float*)d_in[12];
    const float* W_out   = (const float*)d_in[13];
    const float* wxyz    = (const float*)d_in[14];
    const float* bxyz    = (const float*)d_in[15];
    const float* wpqr    = (const float*)d_in[16];
    const float* bpqr    = (const float*)d_in[17];
    float* out = (float*)d_out;

    void* sp = nullptr;
    cudaGetSymbolAddress(&sp, g_scratch);
    float* S = (float*)sp;

    float* f     = S + OFF_F;
    float* u     = S + OFF_U;
    float* xz    = S + OFF_XZ;
    float* xs    = S + OFF_XS;
    float* xdbl  = S + OFF_XDBL;
    float* dtb   = S + OFF_DT;
    float* y     = S + OFF_Y;
    float* feat  = S + OFF_FEAT;
    uint2* wTp   = (uint2*)(S + OFF_WT);

    cudaFuncSetAttribute(conv_tc_kernel,
                         cudaFuncAttributeMaxDynamicSharedMemorySize,
                         CONV_SMEM_TOTAL);

    // (1) prep: weight pack + zero f, xdbl, feat, xz
    prep_zero_kernel<<<(PZ_TOT + 255) / 256, 256>>>(conv_w, S);
    // (2) conv + relu + spatial sum (tensor cores)
    conv_tc_kernel<<<dim3(49, 32), 128, CONV_SMEM_TOTAL>>>(x, wTp, conv_b, f);
    // (3) fc + build_u fused  (64 x 2048 x 512, BM=64, act=3 writes u)
    gemm_tc64_kernel<<<dim3(32, 1, 1), 256>>>(f, 512, fc_w, fc_b, 3,
                                              u, DMODEL, 64, 2048, 512, 0);
    // (4) xz = u @ W_in^T  (128 x 8192 x 2048) — split-K=4 atomic (profiled slot)
    gemm_tc_kernel<<<dim3(128, 1, 4), 256>>>(u, 2048, W_in, nullptr, 0,
                                             xz, 8192, 128, 8192, 2048, 1);
    // (5) depthwise conv1d + silu
    conv1d_silu_kernel<<<1024, 256>>>(xz, c1w, c1b, xs);
    // (6) x_dbl = xs @ W_xproj^T  (128 x 160 x 4096) — split-K=16 atomic
    gemm_tc_kernel<<<dim3(3, 1, 16), 256>>>(xs, 4096, W_xproj, nullptr, 0,
                                            xdbl, 160, 128, 160, 4096, 1);
    // (7) dt = softplus(x_dbl[:, :128] @ W_dt^T + b_dt)  (128 x 4096 x 128)
    gemm_tc_kernel<<<dim3(64, 1, 1), 256>>>(xdbl, 160, W_dt, b_dt, 2,
                                            dtb, 4096, 128, 4096, 128, 0);
    // (8) scan + gating -> y
    scan_kernel<<<1024, 256>>>(xz, xs, xdbl, dtb, A_log, Dv, y);
    // (9) feat = y @ W_out^T  (64 x 2048 x 4096, BM=64, split-K=4 atomic)
    gemm_tc64_kernel<<<dim3(32, 1, 4), 256>>>(y, 4096, W_out, nullptr, 0,
                                              feat, 2048, 64, 2048, 4096, 1);
    // (10) heads
    heads_kernel<<<448, 128>>>(feat, wxyz, bxyz, wpqr, bpqr, out);
}

// round 17
// speedup vs baseline: 1.0383x; 1.0383x over previous
#include <cuda_runtime.h>
#include <math.h>

// ---------------- problem constants ----------------
#define NB      64
#define DMODEL  2048
#define DINNER  4096
#define DSTATE  16
#define DTRANK  128
#define FE      512

// ---------------- scratch layout (floats) ----------------
#define OFF_F     0          // 64*512      conv relu-sum accumulator
#define OFF_U     163840     // 128*2048    mamba input u (rows = b*2+l)
#define OFF_XZ    425984     // 128*8192    xz (x both rows; z only odd rows)
#define OFF_XS    1474560    // 128*4096    silu(conv1d(x))
#define OFF_XDBL  1998848    // 128*160     x_dbl
#define OFF_DT    2019328    // 128*4096    dt (softplus)
#define OFF_Y     2543616    // 64*4096     gated scan output at l=1
#define OFF_FEAT  2805760    // 64*2048     y @ W_out^T
#define OFF_WT    2936832    // 76*512 uint2: packed tf32 conv weights (k,k+4 pairs)
#define SCRATCH_TOTAL 3014656

__device__ float g_scratch[SCRATCH_TOTAL];

// conv_tc dynamic smem layout (bytes) — 64-channel weight chunks (R8 proven config)
#define CONV_SMEM_W     0                    // 76*68 uint2 = 41344
#define CONV_SMEM_ACC   41344                // 2*512 float = 4096
#define CONV_SMEM_IN    45440                // 2*3*35*35 tf32 = 29400
#define CONV_SMEM_TOTAL 74840

// ---------------- tf32 mma helpers ----------------
__device__ __forceinline__ unsigned f2tf32(float v) {
    unsigned r;
    asm("cvt.rna.tf32.f32 %0, %1;" : "=r"(r) : "f"(v));
    return r;
}
__device__ __forceinline__ void mma_tf32(float c[4],
                                         unsigned a0, unsigned a1, unsigned a2, unsigned a3,
                                         unsigned b0, unsigned b1) {
    asm volatile(
        "mma.sync.aligned.m16n8k8.row.col.f32.tf32.tf32.f32 "
        "{%0,%1,%2,%3}, {%4,%5,%6,%7}, {%8,%9}, {%0,%1,%2,%3};"
        : "+f"(c[0]), "+f"(c[1]), "+f"(c[2]), "+f"(c[3])
        : "r"(a0), "r"(a1), "r"(a2), "r"(a3), "r"(b0), "r"(b1));
}

// ---------------- fused prep: conv weight pack + zero ALL accumulators ----------------
#define PZ_WT   38912
#define PZ_XD   59392
#define PZ_FT   190464
#define PZ_F    223232
#define PZ_TOT  1271808
__global__ void prep_zero_kernel(const float* __restrict__ w, float* S) {
    int i = blockIdx.x * blockDim.x + threadIdx.x;
    if (i >= PZ_TOT) return;
    if (i < PZ_WT) {
        int kp = i >> 9, co = i & 511;
        int k0 = (kp >> 2) * 8 + (kp & 3);
        int k1 = k0 + 4;
        float v0 = (k0 < 147) ? w[co * 147 + k0] : 0.f;
        float v1 = (k1 < 147) ? w[co * 147 + k1] : 0.f;
        ((uint2*)(S + OFF_WT))[kp * 512 + co] = make_uint2(f2tf32(v0), f2tf32(v1));
    } else if (i < PZ_XD) {
        S[OFF_XDBL + (i - PZ_WT)] = 0.f;
    } else if (i < PZ_FT) {
        S[OFF_FEAT + (i - PZ_XD)] = 0.f;
    } else if (i < PZ_F) {
        S[OFF_F + (i - PZ_FT)] = 0.f;
    } else {
        S[OFF_XZ + (i - PZ_F)] = 0.f;
    }
}

// ---------------- conv 7x7 s4 p3 + bias + relu + spatial-sum (tensor cores) ----------
// (R8 proven config — unchanged)
__global__ void __launch_bounds__(128)
conv_tc_kernel(const float* __restrict__ x, const uint2* __restrict__ wTp,
               const float* __restrict__ bias, float* __restrict__ f_accum)
{
    extern __shared__ __align__(16) char smem[];
    uint2*    s_w  = reinterpret_cast<uint2*>(smem + CONV_SMEM_W);       // [76][68]
    float*    s_acc = reinterpret_cast<float*>(smem + CONV_SMEM_ACC);    // [2][512]
    unsigned* s_in  = reinterpret_cast<unsigned*>(smem + CONV_SMEM_IN);  // [2][3][35][35] tf32

    const int t    = threadIdx.x;
    const int tile = blockIdx.x;
    const int bp   = blockIdx.y;
    const int oh_base = (tile / 7) * 8;
    const int ow_base = (tile % 7) * 8;
    const int ih0 = oh_base * 4 - 3;
    const int iw0 = ow_base * 4 - 3;

    for (int i = t; i < 1024; i += 128) s_acc[i] = 0.f;

    for (int i = t; i < 2 * 3 * 1225; i += 128) {
        int img = i / 3675;
        int rem = i - img * 3675;
        int ci  = rem / 1225; rem -= ci * 1225;
        int r = rem / 35, c = rem - (rem / 35) * 35;
        int ih = ih0 + r, iw = iw0 + c;
        float v = 0.f;
        int b = bp * 2 + img;
        if ((unsigned)ih < 224u && (unsigned)iw < 224u)
            v = x[((b * 3 + ci) * 224 + ih) * 224 + iw];
        s_in[(img * 3 + ci) * 1225 + r * 35 + c] = f2tf32(v);
    }

    const int lane = t & 31;
    const int w    = t >> 5;
    const int img  = w >> 1;
    const int half = w & 1;
    const int q    = lane >> 2;
    const int j    = lane & 3;
    const int ya = half * 16;
    const int xb = q * 4;
    const unsigned* my_in = s_in + img * 3675 + ya * 35 + xb;

    int o0[19], o1[19];
    #pragma unroll
    for (int ks = 0; ks < 19; ++ks) {
        int k0 = ks * 8 + j, k1 = k0 + 4;
        int kk0 = min(k0, 146), kk1 = min(k1, 146);
        int ci0 = kk0 / 49, r0 = kk0 - ci0 * 49;
        int kh0 = r0 / 7,  kw0 = r0 - kh0 * 7;
        int ci1 = kk1 / 49, r1 = kk1 - ci1 * 49;
        int kh1 = r1 / 7,  kw1 = r1 - kh1 * 7;
        o0[ks] = ci0 * 1225 + kh0 * 35 + kw0;
        o1[ks] = ci1 * 1225 + kh1 * 35 + kw1;
    }

    for (int n0 = 0; n0 < 512; n0 += 64) {
        __syncthreads();
        {
            const uint4* src = reinterpret_cast<const uint4*>(wTp);
            uint4* dst = reinterpret_cast<uint4*>(s_w);
            for (int i = t; i < 76 * 32; i += 128) {
                int row = i >> 5, c = i & 31;
                dst[row * 34 + c] = src[row * 256 + (n0 >> 1) + c];
            }
        }
        __syncthreads();

        float c[2][8][4];
        #pragma unroll
        for (int f2 = 0; f2 < 2; ++f2)
            #pragma unroll
            for (int nf = 0; nf < 8; ++nf)
                #pragma unroll
                for (int u2 = 0; u2 < 4; ++u2) c[f2][nf][u2] = 0.f;

        #pragma unroll
        for (int ks = 0; ks < 19; ++ks) {
            int p0 = o0[ks], p1 = o1[ks];
            unsigned aA0 = my_in[p0];
            unsigned aA1 = my_in[p0 + 140];
            unsigned aA2 = my_in[p1];
            unsigned aA3 = my_in[p1 + 140];
            unsigned aB0 = my_in[p0 + 280];
            unsigned aB1 = my_in[p0 + 420];
            unsigned aB2 = my_in[p1 + 280];
            unsigned aB3 = my_in[p1 + 420];
            const uint2* wr = s_w + (ks * 4 + j) * 68 + q;
            #pragma unroll
            for (int nf = 0; nf < 8; ++nf) {
                uint2 b2 = wr[nf * 8];
                mma_tf32(c[0][nf], aA0, aA1, aA2, aA3, b2.x, b2.y);
                mma_tf32(c[1][nf], aB0, aB1, aB2, aB3, b2.x, b2.y);
            }
        }

        #pragma unroll
        for (int nf = 0; nf < 8; ++nf) {
            int ca = n0 + nf * 8 + 2 * j;
            float bva = bias[ca], bvb = bias[ca + 1];
            float va = fmaxf(c[0][nf][0] + bva, 0.f) + fmaxf(c[0][nf][2] + bva, 0.f)
                     + fmaxf(c[1][nf][0] + bva, 0.f) + fmaxf(c[1][nf][2] + bva, 0.f);
            float vb = fmaxf(c[0][nf][1] + bvb, 0.f) + fmaxf(c[0][nf][3] + bvb, 0.f)
                     + fmaxf(c[1][nf][1] + bvb, 0.f) + fmaxf(c[1][nf][3] + bvb, 0.f);
            #pragma unroll
            for (int off = 16; off >= 4; off >>= 1) {
                va += __shfl_down_sync(0xffffffffu, va, off);
                vb += __shfl_down_sync(0xffffffffu, vb, off);
            }
            if (lane < 4) {
                atomicAdd(&s_acc[img * 512 + ca], va);
                atomicAdd(&s_acc[img * 512 + ca + 1], vb);
            }
        }
    }

    __syncthreads();
    for (int i = t; i < 1024; i += 128) {
        int im = i >> 9, ch = i & 511;
        atomicAdd(&f_accum[(bp * 2 + im) * 512 + ch], s_acc[im * 512 + ch]);
    }
}

// ---------------- BM=128 3xTF32 GEMM (R14-proven: separate hi/lo planes) ----------
#define GT_SA 136
#define GT_SW 72
__global__ void __launch_bounds__(256)
gemm_tc_kernel(const float* __restrict__ A, int lda,
               const float* __restrict__ W,
               const float* __restrict__ bias, int act,
               float* __restrict__ C, int ldc,
               int M, int N, int K, int atomic)
{
    __shared__ unsigned sAh[16 * GT_SA], sAl[16 * GT_SA];
    __shared__ unsigned sWh[16 * GT_SW], sWl[16 * GT_SW];

    const int bm = blockIdx.y * 128;
    const int bn = blockIdx.x * 64;
    const int t = threadIdx.x, lane = t & 31, w = t >> 5;
    const int kPer = K / gridDim.z;
    const int kBeg = blockIdx.z * kPer;
    const int kEnd = kBeg + kPer;

    const int rA0 = t >> 2,   cA = t & 3;
    const int rA1 = rA0 + 64;
    const int gA0 = min(bm + rA0, M - 1);
    const int gA1 = min(bm + rA1, M - 1);
    const int gW  = bn + rA0;
    const bool wOk = (gW < N);

    float acc[8][4];
    #pragma unroll
    for (int nf = 0; nf < 8; ++nf)
        #pragma unroll
        for (int u2 = 0; u2 < 4; ++u2) acc[nf][u2] = 0.f;

    float4 rAv0 = *reinterpret_cast<const float4*>(A + (size_t)gA0 * lda + kBeg + cA * 4);
    float4 rAv1 = *reinterpret_cast<const float4*>(A + (size_t)gA1 * lda + kBeg + cA * 4);
    float4 rWv  = wOk ? *reinterpret_cast<const float4*>(W + (size_t)gW * K + kBeg + cA * 4)
                      : make_float4(0.f, 0.f, 0.f, 0.f);

    for (int k0 = kBeg; k0 < kEnd; k0 += 16) {
        {
            float vv0[4] = {rAv0.x, rAv0.y, rAv0.z, rAv0.w};
            float vv1[4] = {rAv1.x, rAv1.y, rAv1.z, rAv1.w};
            float vvW[4] = {rWv.x, rWv.y, rWv.z, rWv.w};
            #pragma unroll
            for (int e = 0; e < 4; ++e) {
                unsigned h0 = f2tf32(vv0[e]);
                sAh[(cA * 4 + e) * GT_SA + rA0] = h0;
                sAl[(cA * 4 + e) * GT_SA + rA0] = f2tf32(vv0[e] - __uint_as_float(h0));
                unsigned h1 = f2tf32(vv1[e]);
                sAh[(cA * 4 + e) * GT_SA + rA1] = h1;
                sAl[(cA * 4 + e) * GT_SA + rA1] = f2tf32(vv1[e] - __uint_as_float(h1));
                unsigned hw = f2tf32(vvW[e]);
                sWh[(cA * 4 + e) * GT_SW + rA0] = hw;
                sWl[(cA * 4 + e) * GT_SW + rA0] = f2tf32(vvW[e] - __uint_as_float(hw));
            }
        }
        __syncthreads();

        int kn = k0 + 16;
        if (kn < kEnd) {
            rAv0 = *reinterpret_cast<const float4*>(A + (size_t)gA0 * lda + kn + cA * 4);
            rAv1 = *reinterpret_cast<const float4*>(A + (size_t)gA1 * lda + kn + cA * 4);
            if (wOk)
                rWv = *reinterpret_cast<const float4*>(W + (size_t)gW * K + kn + cA * 4);
        }

        #pragma unroll
        for (int ks = 0; ks < 2; ++ks) {
            int kb = ks * 8;
            int ar = w * 16 + (lane >> 2);
            int ac = kb + (lane & 3);
            unsigned ah0 = sAh[ac * GT_SA + ar];
            unsigned ah1 = sAh[ac * GT_SA + ar + 8];
            unsigned ah2 = sAh[(ac + 4) * GT_SA + ar];
            unsigned ah3 = sAh[(ac + 4) * GT_SA + ar + 8];
            unsigned al0 = sAl[ac * GT_SA + ar];
            unsigned al1 = sAl[ac * GT_SA + ar + 8];
            unsigned al2 = sAl[(ac + 4) * GT_SA + ar];
            unsigned al3 = sAl[(ac + 4) * GT_SA + ar + 8];

            #pragma unroll
            for (int nf = 0; nf < 8; ++nf) {
                int bc = nf * 8 + (lane >> 2);
                int br = kb + (lane & 3);
                unsigned bh0 = sWh[br * GT_SW + bc];
                unsigned bh1 = sWh[(br + 4) * GT_SW + bc];
                unsigned bl0 = sWl[br * GT_SW + bc];
                unsigned bl1 = sWl[(br + 4) * GT_SW + bc];
                mma_tf32(acc[nf], ah0, ah1, ah2, ah3, bh0, bh1);
                mma_tf32(acc[nf], ah0, ah1, ah2, ah3, bl0, bl1);
                mma_tf32(acc[nf], al0, al1, al2, al3, bh0, bh1);
            }
        }
        __syncthreads();
    }

    const int mr0 = bm + w * 16 + (lane >> 2);
    const int nc0 = bn + (lane & 3) * 2;
    #pragma unroll
    for (int nf = 0; nf < 8; ++nf) {
        int n = nc0 + nf * 8;
        if (n >= N) continue;
        if (atomic) {
            if (mr0 < M) {
                atomicAdd(&C[(size_t)mr0 * ldc + n],     acc[nf][0]);
                atomicAdd(&C[(size_t)mr0 * ldc + n + 1], acc[nf][1]);
            }
            if (mr0 + 8 < M) {
                atomicAdd(&C[(size_t)(mr0 + 8) * ldc + n],     acc[nf][2]);
                atomicAdd(&C[(size_t)(mr0 + 8) * ldc + n + 1], acc[nf][3]);
            }
        } else {
            float b0 = bias ? bias[n] : 0.f;
            float b1 = bias ? bias[n + 1] : 0.f;
            float v00 = acc[nf][0] + b0, v01 = acc[nf][1] + b1;
            float v10 = acc[nf][2] + b0, v11 = acc[nf][3] + b1;
            if (act == 2) {
                v00 = (v00 > 20.f) ? v00 : log1pf(expf(v00));
                v01 = (v01 > 20.f) ? v01 : log1pf(expf(v01));
                v10 = (v10 > 20.f) ? v10 : log1pf(expf(v10));
                v11 = (v11 > 20.f) ? v11 : log1pf(expf(v11));
            }
            if (mr0 < M) {
                C[(size_t)mr0 * ldc + n]     = v00;
                C[(size_t)mr0 * ldc + n + 1] = v01;
            }
            if (mr0 + 8 < M) {
                C[(size_t)(mr0 + 8) * ldc + n]     = v10;
                C[(size_t)(mr0 + 8) * ldc + n + 1] = v11;
            }
        }
    }
}

// ---------------- BM=64 3xTF32 GEMM (R14-proven; fc-fused epilogue act=3) ----------
#define GT64_S 72
__global__ void __launch_bounds__(256)
gemm_tc64_kernel(const float* __restrict__ A, int lda,
                 const float* __restrict__ W,
                 const float* __restrict__ bias, int act,
                 float* __restrict__ C, int ldc,
                 int M, int N, int K, int atomic)
{
    __shared__ unsigned sAh[16 * GT64_S], sAl[16 * GT64_S];
    __shared__ unsigned sWh[16 * GT64_S], sWl[16 * GT64_S];

    const int bm = blockIdx.y * 64;
    const int bn = blockIdx.x * 64;
    const int t = threadIdx.x, lane = t & 31, w = t >> 5;
    const int kPer = K / gridDim.z;
    const int kBeg = blockIdx.z * kPer;
    const int kEnd = kBeg + kPer;

    const int rA = t >> 2, cA = t & 3;
    const int gA = min(bm + rA, M - 1);
    const int gW = bn + rA;
    const bool wOk = (gW < N);

    float acc[4][4];
    #pragma unroll
    for (int nf = 0; nf < 4; ++nf)
        #pragma unroll
        for (int u2 = 0; u2 < 4; ++u2) acc[nf][u2] = 0.f;

    float4 rAv = *reinterpret_cast<const float4*>(A + (size_t)gA * lda + kBeg + cA * 4);
    float4 rWv = wOk ? *reinterpret_cast<const float4*>(W + (size_t)gW * K + kBeg + cA * 4)
                     : make_float4(0.f, 0.f, 0.f, 0.f);

    for (int k0 = kBeg; k0 < kEnd; k0 += 16) {
        {
            float vvA[4] = {rAv.x, rAv.y, rAv.z, rAv.w};
            float vvW[4] = {rWv.x, rWv.y, rWv.z, rWv.w};
            #pragma unroll
            for (int e = 0; e < 4; ++e) {
                unsigned ha = f2tf32(vvA[e]);
                sAh[(cA * 4 + e) * GT64_S + rA] = ha;
                sAl[(cA * 4 + e) * GT64_S + rA] = f2tf32(vvA[e] - __uint_as_float(ha));
                unsigned hw = f2tf32(vvW[e]);
                sWh[(cA * 4 + e) * GT64_S + rA] = hw;
                sWl[(cA * 4 + e) * GT64_S + rA] = f2tf32(vvW[e] - __uint_as_float(hw));
            }
        }
        __syncthreads();

        int kn = k0 + 16;
        if (kn < kEnd) {
            rAv = *reinterpret_cast<const float4*>(A + (size_t)gA * lda + kn + cA * 4);
            if (wOk)
                rWv = *reinterpret_cast<const float4*>(W + (size_t)gW * K + kn + cA * 4);
        }

        #pragma unroll
        for (int ks = 0; ks < 2; ++ks) {
            int kb = ks * 8;
            int ar = (w & 3) * 16 + (lane >> 2);
            int ac = kb + (lane & 3);
            unsigned ah0 = sAh[ac * GT64_S + ar];
            unsigned ah1 = sAh[ac * GT64_S + ar + 8];
            unsigned ah2 = sAh[(ac + 4) * GT64_S + ar];
            unsigned ah3 = sAh[(ac + 4) * GT64_S + ar + 8];
            unsigned al0 = sAl[ac * GT64_S + ar];
            unsigned al1 = sAl[ac * GT64_S + ar + 8];
            unsigned al2 = sAl[(ac + 4) * GT64_S + ar];
            unsigned al3 = sAl[(ac + 4) * GT64_S + ar + 8];

            #pragma unroll
            for (int nf = 0; nf < 4; ++nf) {
                int bc = (w >> 2) * 32 + nf * 8 + (lane >> 2);
                int br = kb + (lane & 3);
                unsigned bh0 = sWh[br * GT64_S + bc];
                unsigned bh1 = sWh[(br + 4) * GT64_S + bc];
                unsigned bl0 = sWl[br * GT64_S + bc];
                unsigned bl1 = sWl[(br + 4) * GT64_S + bc];
                mma_tf32(acc[nf], ah0, ah1, ah2, ah3, bh0, bh1);
                mma_tf32(acc[nf], ah0, ah1, ah2, ah3, bl0, bl1);
                mma_tf32(acc[nf], al0, al1, al2, al3, bh0, bh1);
            }
        }
        __syncthreads();
    }

    const int mr0 = bm + (w & 3) * 16 + (lane >> 2);
    const int nc0 = bn + (w >> 2) * 32 + (lane & 3) * 2;
    #pragma unroll
    for (int nf = 0; nf < 4; ++nf) {
        int n = nc0 + nf * 8;
        if (n >= N) continue;
        if (atomic) {
            if (mr0 < M) {
                atomicAdd(&C[(size_t)mr0 * ldc + n],     acc[nf][0]);
                atomicAdd(&C[(size_t)mr0 * ldc + n + 1], acc[nf][1]);
            }
            if (mr0 + 8 < M) {
                atomicAdd(&C[(size_t)(mr0 + 8) * ldc + n],     acc[nf][2]);
                atomicAdd(&C[(size_t)(mr0 + 8) * ldc + n + 1], acc[nf][3]);
            }
        } else if (act == 3) {
            float b0 = bias[n], b1 = bias[n + 1];
            #pragma unroll
            for (int h = 0; h < 2; ++h) {
                int m = mr0 + h * 8;
                if (m >= M) continue;
                float v0 = fmaxf(acc[nf][h * 2 + 0] * (1.f / 3136.f) + b0, 0.f);
                float v1 = fmaxf(acc[nf][h * 2 + 1] * (1.f / 3136.f) + b1, 0.f);
                C[(size_t)(2 * m + 1) * DMODEL + n]     = v0;
                C[(size_t)(2 * m + 1) * DMODEL + n + 1] = v1;
                C[(size_t)(2 * m) * DMODEL + (DMODEL - 1 - n)]       = v0;
                C[(size_t)(2 * m) * DMODEL + (DMODEL - 1 - (n + 1))] = v1;
            }
        } else {
            float b0 = bias ? bias[n] : 0.f;
            float b1 = bias ? bias[n + 1] : 0.f;
            if (mr0 < M) {
                C[(size_t)mr0 * ldc + n]     = acc[nf][0] + b0;
                C[(size_t)mr0 * ldc + n + 1] = acc[nf][1] + b1;
            }
            if (mr0 + 8 < M) {
                C[(size_t)(mr0 + 8) * ldc + n]     = acc[nf][2] + b0;
                C[(size_t)(mr0 + 8) * ldc + n + 1] = acc[nf][3] + b1;
            }
        }
    }
}

// ---------------- depthwise conv1d (L=2, causal k=4) + silu ----------------
__global__ void conv1d_silu_kernel(const float* __restrict__ xz, const float* __restrict__ w,
                                   const float* __restrict__ bias, float* __restrict__ xs)
{
    int idx = blockIdx.x * blockDim.x + threadIdx.x;
    if (idx >= NB * DINNER) return;
    int b = idx >> 12, e = idx & 4095;
    float x0 = xz[(2 * b) * (2 * DINNER) + e];
    float x1 = xz[(2 * b + 1) * (2 * DINNER) + e];
    float w2 = w[e * 4 + 2], w3 = w[e * 4 + 3];
    float bv = bias[e];
    float v0 = x0 * w3 + bv;
    float v1 = x0 * w2 + x1 * w3 + bv;
    xs[(2 * b) * DINNER + e]     = v0 / (1.f + expf(-v0));
    xs[(2 * b + 1) * DINNER + e] = v1 / (1.f + expf(-v1));
}

// ---------------- selective scan (L=2, closed form) + D skip + silu(z) gating --------
__global__ void scan_kernel(const float* __restrict__ xz, const float* __restrict__ xs,
                            const float* __restrict__ xdbl, const float* __restrict__ dt,
                            const float* __restrict__ A_log, const float* __restrict__ Dv,
                            float* __restrict__ y)
{
    int idx = blockIdx.x * blockDim.x + threadIdx.x;
    if (idx >= NB * DINNER) return;
    int b = idx >> 12, e = idx & 4095;

    float dt0 = dt[(2 * b) * DINNER + e];
    float dt1 = dt[(2 * b + 1) * DINNER + e];
    float x0  = xs[(2 * b) * DINNER + e];
    float x1  = xs[(2 * b + 1) * DINNER + e];
    float z1  = xz[(2 * b + 1) * (2 * DINNER) + DINNER + e];

    const float* bc0 = xdbl + (2 * b) * 160;
    const float* bc1 = xdbl + (2 * b + 1) * 160;

    float acc = 0.f;
    #pragma unroll
    for (int n = 0; n < DSTATE; ++n) {
        float Ae = -expf(A_log[e * DSTATE + n]);
        float h = dt0 * bc0[DTRANK + n] * x0;
        h = h * expf(dt1 * Ae) + dt1 * bc1[DTRANK + n] * x1;
        acc += h * bc1[DTRANK + DSTATE + n];
    }
    float yv = acc + x1 * Dv[e];
    float sg = z1 / (1.f + expf(-z1));
    y[b * DINNER + e] = yv * sg;
}

// ---------------- output heads ----------------
__global__ void heads_kernel(const float* __restrict__ feat,
                             const float* __restrict__ wxyz, const float* __restrict__ bxyz,
                             const float* __restrict__ wpqr, const float* __restrict__ bpqr,
                             float* __restrict__ out)
{
    int b = blockIdx.x / 7, j = blockIdx.x % 7;
    const float* wrow = (j < 3) ? (wxyz + j * DMODEL) : (wpqr + (j - 3) * DMODEL);
    float bias = (j < 3) ? bxyz[j] : bpqr[j - 3];

    float s = 0.f;
    for (int i = threadIdx.x; i < DMODEL; i += 128)
        s += feat[b * DMODEL + i] * wrow[i];

    __shared__ float red[4];
    #pragma unroll
    for (int off = 16; off; off >>= 1) s += __shfl_down_sync(0xffffffffu, s, off);
    if ((threadIdx.x & 31) == 0) red[threadIdx.x >> 5] = s;
    __syncthreads();
    if (threadIdx.x == 0)
        out[b * 7 + j] = red[0] + red[1] + red[2] + red[3] + bias;
}

// ---------------- launcher ----------------
extern "C" void kernel_launch(void* const* d_in, const int* in_sizes, int n_in,
                              void* d_out, int out_size)
{
    const float* x       = (const float*)d_in[0];
    const float* conv_w  = (const float*)d_in[1];
    const float* conv_b  = (const float*)d_in[2];
    const float* fc_w    = (const float*)d_in[3];
    const float* fc_b    = (const float*)d_in[4];
    const float* W_in    = (const float*)d_in[5];
    const float* c1w     = (const float*)d_in[6];
    const float* c1b     = (const float*)d_in[7];
    const float* W_xproj = (const float*)d_in[8];
    const float* W_dt    = (const float*)d_in[9];
    const float* b_dt    = (const float*)d_in[10];
    const float* A_log   = (const float*)d_in[11];
    const float* Dv      = (const float*)d_in[12];
    const float* W_out   = (const float*)d_in[13];
    const float* wxyz    = (const float*)d_in[14];
    const float* bxyz    = (const float*)d_in[15];
    const float* wpqr    = (const float*)d_in[16];
    const float* bpqr    = (const float*)d_in[17];
    float* out = (float*)d_out;

    void* sp = nullptr;
    cudaGetSymbolAddress(&sp, g_scratch);
    float* S = (float*)sp;

    float* f     = S + OFF_F;
    float* u     = S + OFF_U;
    float* xz    = S + OFF_XZ;
    float* xs    = S + OFF_XS;
    float* xdbl  = S + OFF_XDBL;
    float* dtb   = S + OFF_DT;
    float* y     = S + OFF_Y;
    float* feat  = S + OFF_FEAT;
    uint2* wTp   = (uint2*)(S + OFF_WT);

    cudaFuncSetAttribute(conv_tc_kernel,
                         cudaFuncAttributeMaxDynamicSharedMemorySize,
                         CONV_SMEM_TOTAL);

    // (1) prep: weight pack + zero f, xdbl, feat, xz
    prep_zero_kernel<<<(PZ_TOT + 255) / 256, 256>>>(conv_w, S);
    // (2) conv + relu + spatial sum (tensor cores)
    conv_tc_kernel<<<dim3(49, 32), 128, CONV_SMEM_TOTAL>>>(x, wTp, conv_b, f);
    // (3) fc + build_u fused  (64 x 2048 x 512, BM=64, act=3 writes u)
    gemm_tc64_kernel<<<dim3(32, 1, 1), 256>>>(f, 512, fc_w, fc_b, 3,
                                              u, DMODEL, 64, 2048, 512, 0);
    // (4a) x-part of xz: all 128 rows x 4096 cols — split-K=2 atomic (profiled slot)
    gemm_tc_kernel<<<dim3(64, 1, 2), 256>>>(u, 2048, W_in, nullptr, 0,
                                            xz, 8192, 128, 4096, 2048, 1);
    // (4b) z-part of xz: ODD rows only (l=1), cols 4096..8191 — skips the unused
    //      z at l=0 (25% of the original xz GEMM). Row m -> u row 2m+1 via
    //      A = u + DMODEL, lda = 2*DMODEL; C row m -> xz row 2m+1 via
    //      C = xz + 8192 + 4096, ldc = 16384. Split-K=2 atomic (region zeroed).
    gemm_tc64_kernel<<<dim3(64, 1, 2), 256>>>(u + DMODEL, 2 * DMODEL,
                                              W_in + (size_t)DINNER * DMODEL,
                                              nullptr, 0,
                                              xz + 2 * DINNER + DINNER, 2 * 2 * DINNER,
                                              64, 4096, 2048, 1);
    // (5) depthwise conv1d + silu
    conv1d_silu_kernel<<<1024, 256>>>(xz, c1w, c1b, xs);
    // (6) x_dbl = xs @ W_xproj^T  (128 x 160 x 4096) — split-K=16 atomic
    gemm_tc_kernel<<<dim3(3, 1, 16), 256>>>(xs, 4096, W_xproj, nullptr, 0,
                                            xdbl, 160, 128, 160, 4096, 1);
    // (7) dt = softplus(x_dbl[:, :128] @ W_dt^T + b_dt)  (128 x 4096 x 128)
    gemm_tc_kernel<<<dim3(64, 1, 1), 256>>>(xdbl, 160, W_dt, b_dt, 2,
                                            dtb, 4096, 128, 4096, 128, 0);
    // (8) scan + gating -> y
    scan_kernel<<<1024, 256>>>(xz, xs, xdbl, dtb, A_log, Dv, y);
    // (9) feat = y @ W_out^T  (64 x 2048 x 4096, BM=64, split-K=4 atomic)
    gemm_tc64_kernel<<<dim3(32, 1, 4), 256>>>(y, 4096, W_out, nullptr, 0,
                                              feat, 2048, 64, 2048, 4096, 1);
    // (10) heads
    heads_kernel<<<448, 128>>>(feat, wxyz, bxyz, wpqr, bpqr, out);
}